// round 13
// baseline (speedup 1.0000x reference)
#include <cuda_runtime.h>

// Problem constants (B=8, C=64, H=W=256, GROUPS=32, PATCH=8)
#define HW      65536
#define CHN     64
#define BATCH   8
#define NPIX    128           // pixels per conv block
#define EPSV    1e-5f

typedef unsigned long long u64;

// ---- packed f32x2 helpers (sm_103a; ptxas never auto-fuses these) ----------
__device__ __forceinline__ u64 pack2(float lo, float hi) {
    u64 r;
    asm("mov.b64 %0, {%1, %2};" : "=l"(r) : "f"(lo), "f"(hi));
    return r;
}
__device__ __forceinline__ void unpack2(u64 v, float& lo, float& hi) {
    asm("mov.b64 {%0, %1}, %2;" : "=f"(lo), "=f"(hi) : "l"(v));
}
__device__ __forceinline__ void fma2(u64& d, u64 a, u64 b) {
    asm("fma.rn.f32x2 %0, %1, %2, %0;" : "+l"(d) : "l"(a), "l"(b));
}

// ---------------- scratch (device globals; no allocation allowed) ----------
__device__ float g_qk[2u * BATCH * CHN * HW];     // [t][b][c][hw]  (q then k)
__device__ float g_psum[2 * BATCH * 32 * 512];    // per-block partial sums
__device__ float g_pss [2 * BATCH * 32 * 512];    // per-block partial sum-of-squares
__device__ float g_scale[2 * BATCH * CHN];        // GN folded: per (t,b,c) scale
__device__ float g_bias [2 * BATCH * CHN];        // GN folded: per (t,b,c) bias
__device__ float g_Wt[2 * CHN * CHN];             // W transposed: [t][c][o]

// ---------------- K0: transpose weights into scratch ------------------------
__global__ void k_wt(const float* __restrict__ Wq, const float* __restrict__ Wk)
{
    const float* Wm = blockIdx.x ? Wk : Wq;
    float* o = g_Wt + blockIdx.x * CHN * CHN;
    const int tid = threadIdx.x;
#pragma unroll
    for (int i = 0; i < 16; ++i) {
        int e = i * 256 + tid;
        int r = e >> 6, c = e & 63;
        o[c * CHN + r] = Wm[e];
    }
}

// ---------------- K1: 1x1 conv (GEMM, f32x2) + group-stat partials ----------
__global__ __launch_bounds__(256) void k_conv(const float* __restrict__ xlow,
                                              const float* __restrict__ xhigh)
{
    __shared__ float Xs[64][128];   // [c][pixel]  32KB
    __shared__ float Ws[64][64];    // [c][o]      16KB

    const int t   = blockIdx.z;
    const float* x = t ? xhigh : xlow;
    const int b   = blockIdx.y;
    const int tid = threadIdx.x;
    const int p0  = blockIdx.x * NPIX;

    {
        const float4* wt4 = reinterpret_cast<const float4*>(g_Wt + t * CHN * CHN);
        float4* ws4 = reinterpret_cast<float4*>(&Ws[0][0]);
#pragma unroll
        for (int i = 0; i < 4; ++i) ws4[i * 256 + tid] = wt4[i * 256 + tid];
    }
    {
        const float4* xb4 = reinterpret_cast<const float4*>(x + (size_t)b * CHN * HW + p0);
#pragma unroll
        for (int i = 0; i < 8; ++i) {
            int e = i * 256 + tid;
            int c = e >> 5, q = e & 31;
            *reinterpret_cast<float4*>(&Xs[c][q * 4]) = xb4[(size_t)c * (HW / 4) + q];
        }
    }
    __syncthreads();

    const int tx = tid & 31;
    const int ty = tid >> 5;

    u64 acc2[4][4];
#pragma unroll
    for (int a = 0; a < 4; ++a)
#pragma unroll
        for (int p = 0; p < 4; ++p) acc2[a][p] = 0ull;

#pragma unroll 8
    for (int k = 0; k < 64; ++k) {
        float4 xv = *reinterpret_cast<const float4*>(&Xs[k][tx * 4]);
        ulonglong2 w01 = *reinterpret_cast<const ulonglong2*>(&Ws[k][ty * 8]);
        ulonglong2 w23 = *reinterpret_cast<const ulonglong2*>(&Ws[k][ty * 8 + 4]);
        u64 wp[4] = {w01.x, w01.y, w23.x, w23.y};
        u64 xd[4] = {pack2(xv.x, xv.x), pack2(xv.y, xv.y),
                     pack2(xv.z, xv.z), pack2(xv.w, xv.w)};
#pragma unroll
        for (int a = 0; a < 4; ++a)
#pragma unroll
            for (int p = 0; p < 4; ++p)
                fma2(acc2[a][p], wp[a], xd[p]);
    }

    float* ob = g_qk + (size_t)t * BATCH * CHN * HW + (size_t)b * CHN * HW + p0;
#pragma unroll
    for (int ap = 0; ap < 4; ++ap) {
        float lo[4], hi[4];
#pragma unroll
        for (int p = 0; p < 4; ++p) unpack2(acc2[ap][p], lo[p], hi[p]);
        int o0 = ty * 8 + 2 * ap;
        *reinterpret_cast<float4*>(&ob[(size_t)o0 * HW + tx * 4]) =
            make_float4(lo[0], lo[1], lo[2], lo[3]);
        *reinterpret_cast<float4*>(&ob[(size_t)(o0 + 1) * HW + tx * 4]) =
            make_float4(hi[0], hi[1], hi[2], hi[3]);

        float s = 0.f, ss = 0.f;
#pragma unroll
        for (int p = 0; p < 4; ++p) {
            s  += lo[p] + hi[p];
            ss += lo[p] * lo[p] + hi[p] * hi[p];
        }
#pragma unroll
        for (int m = 16; m > 0; m >>= 1) {
            s  += __shfl_xor_sync(0xffffffffu, s,  m);
            ss += __shfl_xor_sync(0xffffffffu, ss, m);
        }
        if (tx == 0) {
            int g   = ty * 4 + ap;
            int idx = ((t * BATCH + b) * 32 + g) * 512 + blockIdx.x;
            g_psum[idx] = s;
            g_pss[idx]  = ss;
        }
    }
}

// ---------------- K2: finalize stats -> per-channel scale/bias --------------
__global__ void k_stats(const float* __restrict__ gq, const float* __restrict__ bq,
                        const float* __restrict__ gk, const float* __restrict__ bk)
{
    const int id  = blockIdx.x;
    const int tid = threadIdx.x;
    const float* ps = g_psum + (size_t)id * 512;
    const float* pq = g_pss  + (size_t)id * 512;
    float s  = ps[tid] + ps[tid + 256];
    float ss = pq[tid] + pq[tid + 256];
#pragma unroll
    for (int m = 16; m > 0; m >>= 1) {
        s  += __shfl_xor_sync(0xffffffffu, s,  m);
        ss += __shfl_xor_sync(0xffffffffu, ss, m);
    }
    __shared__ float sh[16];
    int w = tid >> 5;
    if ((tid & 31) == 0) { sh[w] = s; sh[8 + w] = ss; }
    __syncthreads();
    if (tid == 0) {
        float S = 0.f, SS = 0.f;
#pragma unroll
        for (int i = 0; i < 8; ++i) { S += sh[i]; SS += sh[8 + i]; }
        const float inv  = 1.0f / 131072.0f;
        float mean = S * inv;
        float var  = SS * inv - mean * mean;
        float rstd = rsqrtf(var + EPSV);
        int t = id >> 8, b = (id >> 5) & 7, g = id & 31;
        const float* ga = t ? gk : gq;
        const float* be = t ? bk : bq;
#pragma unroll
        for (int j = 0; j < 2; ++j) {
            int c = g * 2 + j;
            float sc = rstd * ga[c];
            g_scale[(t * BATCH + b) * CHN + c] = sc;
            g_bias [(t * BATCH + b) * CHN + c] = be[c] - mean * sc;
        }
    }
}

// ---------------- K3: windowed cross-attention + residual -------------------
// 256 threads = 2 windows x 128 threads. Per window: 8x4 register tiles,
// f32x2 FMA. smem 69.6KB/block, launch_bounds(256,3) -> 3 blocks/SM (37.5% occ).
__global__ __launch_bounds__(256, 3) void k_attn(const float* __restrict__ xlow,
                                                 float* __restrict__ outp)
{
    extern __shared__ float sm[];
    const int tid = threadIdx.x;
    const int win = tid >> 7;           // window within block
    const int wt  = tid & 127;          // thread within window
    float (*bufA)[68] = reinterpret_cast<float(*)[68]>(sm + win * 8704);         // q -> K_T
    float (*bufK)[68] = reinterpret_cast<float(*)[68]>(sm + win * 8704 + 4352);  // k -> P_T

    const int b  = blockIdx.y;
    const int wi = blockIdx.x * 2 + win;
    const int h0 = (wi >> 5) * 8, w0 = (wi & 31) * 8;
    const size_t gb = (size_t)b * CHN * HW;
    const float* qg = g_qk + gb;
    const float* kg = g_qk + (size_t)BATCH * CHN * HW + gb;
    const float* scq = g_scale + b * CHN;
    const float* biq = g_bias  + b * CHN;
    const float* sck = g_scale + (BATCH + b) * CHN;
    const float* bik = g_bias  + (BATCH + b) * CHN;

    // ---- load q,k with folded GroupNorm, channel-major [c][px], float4 ----
#pragma unroll
    for (int i = 0; i < 8; ++i) {
        int e = i * 128 + wt;
        int c = e >> 4, f = e & 15;          // px = 4f..4f+3
        size_t ga = (size_t)c * HW + (size_t)(h0 + (f >> 1)) * 256 + (w0 + (f & 1) * 4);
        float4 qv = *reinterpret_cast<const float4*>(qg + ga);
        float4 kv = *reinterpret_cast<const float4*>(kg + ga);
        float sq = scq[c], bq_ = biq[c];
        float sk = sck[c], bk_ = bik[c];
        *reinterpret_cast<float4*>(&bufA[c][f * 4]) =
            make_float4(qv.x * sq + bq_, qv.y * sq + bq_, qv.z * sq + bq_, qv.w * sq + bq_);
        *reinterpret_cast<float4*>(&bufK[c][f * 4]) =
            make_float4(kv.x * sk + bk_, kv.y * sk + bk_, kv.z * sk + bk_, kv.w * sk + bk_);
    }
    __syncthreads();

    const int tx = wt & 15;    // key-col group (4 cols)
    const int ty = wt >> 4;    // query-row group (8 rows)

    // ---- GEMM1: S[q][k] = sum_c q[c][q] * k[c][k], 8x4 tile, f32x2 ----
    u64 acc[8][2];
#pragma unroll
    for (int i = 0; i < 8; ++i) { acc[i][0] = 0ull; acc[i][1] = 0ull; }

#pragma unroll 8
    for (int k = 0; k < 64; ++k) {
        float4 q0 = *reinterpret_cast<const float4*>(&bufA[k][ty * 8]);
        float4 q1 = *reinterpret_cast<const float4*>(&bufA[k][ty * 8 + 4]);
        ulonglong2 kv = *reinterpret_cast<const ulonglong2*>(&bufK[k][tx * 4]);
        u64 qd[8] = {pack2(q0.x, q0.x), pack2(q0.y, q0.y), pack2(q0.z, q0.z), pack2(q0.w, q0.w),
                     pack2(q1.x, q1.x), pack2(q1.y, q1.y), pack2(q1.z, q1.z), pack2(q1.w, q1.w)};
#pragma unroll
        for (int i = 0; i < 8; ++i) {
            fma2(acc[i][0], qd[i], kv.x);
            fma2(acc[i][1], qd[i], kv.y);
        }
    }

    // ---- softmax over key dim (4 local + 16-lane tx group), scale 1/8 ----
    float p[8][4];
#pragma unroll
    for (int i = 0; i < 8; ++i) {
        unpack2(acc[i][0], p[i][0], p[i][1]);
        unpack2(acc[i][1], p[i][2], p[i][3]);
#pragma unroll
        for (int j = 0; j < 4; ++j) p[i][j] *= 0.125f;
        float m = fmaxf(fmaxf(p[i][0], p[i][1]), fmaxf(p[i][2], p[i][3]));
#pragma unroll
        for (int msk = 8; msk > 0; msk >>= 1)
            m = fmaxf(m, __shfl_xor_sync(0xffffffffu, m, msk));
        float r = 0.f;
#pragma unroll
        for (int j = 0; j < 4; ++j) { p[i][j] = __expf(p[i][j] - m); r += p[i][j]; }
#pragma unroll
        for (int msk = 8; msk > 0; msk >>= 1)
            r += __shfl_xor_sync(0xffffffffu, r, msk);
        float inv = __fdividef(1.0f, r);
#pragma unroll
        for (int j = 0; j < 4; ++j) p[i][j] *= inv;
    }
    __syncthreads();   // GEMM1 reads of bufA/bufK complete

    // ---- K_T into bufA (q dead): bufA[px][c] = bufK[c][px] ----
    {
        const int col = wt & 63;
        const int r0  = (wt >> 6) * 32;
#pragma unroll 8
        for (int i = 0; i < 32; ++i) {
            float v = bufK[r0 + i][col];   // row-major read: conflict-free
            bufA[col][r0 + i] = v;         // column write: 4-way
        }
    }
    __syncthreads();   // all K_T reads of bufK done

    // ---- P_T into bufK directly from registers: bufK[k][q] = P[q][k] ----
#pragma unroll
    for (int i = 0; i < 8; ++i)
#pragma unroll
        for (int j = 0; j < 4; ++j)
            bufK[tx * 4 + j][ty * 8 + i] = p[i][j];
    __syncthreads();

    // ---- GEMM2: out[q][c] = sum_kp P_T[kp][q] * K_T[kp][c], 8x4 tile ----
    u64 o2[8][2];
#pragma unroll
    for (int i = 0; i < 8; ++i) { o2[i][0] = 0ull; o2[i][1] = 0ull; }

#pragma unroll 8
    for (int k = 0; k < 64; ++k) {
        float4 p0 = *reinterpret_cast<const float4*>(&bufK[k][ty * 8]);
        float4 p1 = *reinterpret_cast<const float4*>(&bufK[k][ty * 8 + 4]);
        ulonglong2 kv = *reinterpret_cast<const ulonglong2*>(&bufA[k][tx * 4]);
        u64 pd[8] = {pack2(p0.x, p0.x), pack2(p0.y, p0.y), pack2(p0.z, p0.z), pack2(p0.w, p0.w),
                     pack2(p1.x, p1.x), pack2(p1.y, p1.y), pack2(p1.z, p1.z), pack2(p1.w, p1.w)};
#pragma unroll
        for (int i = 0; i < 8; ++i) {
            fma2(o2[i][0], pd[i], kv.x);
            fma2(o2[i][1], pd[i], kv.y);
        }
    }

    // ---- epilogue: residual add + direct global stores ----
    // thread owns q rows ty*8..+7 = window row ty, cols w0..w0+7; channels tx*4..+3
    const float* xb = xlow + gb;
    float* ob = outp + gb;
#pragma unroll
    for (int jp = 0; jp < 2; ++jp) {
        float lo[8], hi[8];
#pragma unroll
        for (int i = 0; i < 8; ++i) unpack2(o2[i][jp], lo[i], hi[i]);
        int c0 = tx * 4 + jp * 2;
        size_t base = (size_t)c0 * HW + (size_t)(h0 + ty) * 256 + w0;
        float4 r0 = *reinterpret_cast<const float4*>(xb + base);
        float4 r1 = *reinterpret_cast<const float4*>(xb + base + 4);
        *reinterpret_cast<float4*>(ob + base) =
            make_float4(lo[0] + r0.x, lo[1] + r0.y, lo[2] + r0.z, lo[3] + r0.w);
        *reinterpret_cast<float4*>(ob + base + 4) =
            make_float4(lo[4] + r1.x, lo[5] + r1.y, lo[6] + r1.z, lo[7] + r1.w);
        size_t base2 = base + HW;
        float4 r2 = *reinterpret_cast<const float4*>(xb + base2);
        float4 r3 = *reinterpret_cast<const float4*>(xb + base2 + 4);
        *reinterpret_cast<float4*>(ob + base2) =
            make_float4(hi[0] + r2.x, hi[1] + r2.y, hi[2] + r2.z, hi[3] + r2.w);
        *reinterpret_cast<float4*>(ob + base2 + 4) =
            make_float4(hi[4] + r3.x, hi[5] + r3.y, hi[6] + r3.z, hi[7] + r3.w);
    }
}

// ---------------- launch -----------------------------------------------------
extern "C" void kernel_launch(void* const* d_in, const int* in_sizes, int n_in,
                              void* d_out, int out_size)
{
    (void)in_sizes; (void)n_in; (void)out_size;
    const float* x_low  = (const float*)d_in[0];
    const float* x_high = (const float*)d_in[1];
    const float* Wq = (const float*)d_in[2];
    const float* Wk = (const float*)d_in[3];
    const float* gq = (const float*)d_in[4];
    const float* bq = (const float*)d_in[5];
    const float* gk = (const float*)d_in[6];
    const float* bk = (const float*)d_in[7];
    float* out = (float*)d_out;

    const int attn_smem = 2 * 2 * 64 * 68 * 4;   // 69632 B
    cudaFuncSetAttribute(k_attn, cudaFuncAttributeMaxDynamicSharedMemorySize, attn_smem);

    k_wt  <<<2, 256>>>(Wq, Wk);
    k_conv<<<dim3(512, BATCH, 2), 256>>>(x_low, x_high);
    k_stats<<<512, 256>>>(gq, bq, gk, bk);
    k_attn<<<dim3(512, BATCH), 256, attn_smem>>>(x_low, out);
}

// round 14
// speedup vs baseline: 1.0402x; 1.0402x over previous
#include <cuda_runtime.h>

// Problem constants (B=8, C=64, H=W=256, GROUPS=32, PATCH=8)
#define HW      65536
#define CHN     64
#define BATCH   8
#define NPIX    128           // pixels per conv block
#define EPSV    1e-5f

typedef unsigned long long u64;

// ---- packed f32x2 helpers (sm_103a; ptxas never auto-fuses these) ----------
__device__ __forceinline__ u64 pack2(float lo, float hi) {
    u64 r;
    asm("mov.b64 %0, {%1, %2};" : "=l"(r) : "f"(lo), "f"(hi));
    return r;
}
__device__ __forceinline__ void unpack2(u64 v, float& lo, float& hi) {
    asm("mov.b64 {%0, %1}, %2;" : "=f"(lo), "=f"(hi) : "l"(v));
}
__device__ __forceinline__ void fma2(u64& d, u64 a, u64 b) {
    asm("fma.rn.f32x2 %0, %1, %2, %0;" : "+l"(d) : "l"(a), "l"(b));
}

// ---------------- scratch (device globals; no allocation allowed) ----------
__device__ float g_qk[2u * BATCH * CHN * HW];     // [t][b][c][hw]  (q then k)
__device__ float g_psum[2 * BATCH * 32 * 512];    // per-block partial sums
__device__ float g_pss [2 * BATCH * 32 * 512];    // per-block partial sum-of-squares
__device__ float g_scale[2 * BATCH * CHN];        // GN folded: per (t,b,c) scale
__device__ float g_bias [2 * BATCH * CHN];        // GN folded: per (t,b,c) bias
__device__ float g_Wt[2 * CHN * CHN];             // W transposed: [t][c][o]

// ---------------- K0: transpose weights into scratch ------------------------
__global__ void k_wt(const float* __restrict__ Wq, const float* __restrict__ Wk)
{
    const float* Wm = blockIdx.x ? Wk : Wq;
    float* o = g_Wt + blockIdx.x * CHN * CHN;
    const int tid = threadIdx.x;
#pragma unroll
    for (int i = 0; i < 16; ++i) {
        int e = i * 256 + tid;
        int r = e >> 6, c = e & 63;
        o[c * CHN + r] = Wm[e];
    }
}

// ---------------- K1: 1x1 conv (GEMM, f32x2, prefetched) + stat partials ----
__global__ __launch_bounds__(256, 3) void k_conv(const float* __restrict__ xlow,
                                                 const float* __restrict__ xhigh)
{
    __shared__ float Xs[64][128];   // [c][pixel]  32KB
    __shared__ float Ws[64][64];    // [c][o]      16KB

    const int t   = blockIdx.z;
    const float* x = t ? xhigh : xlow;
    const int b   = blockIdx.y;
    const int tid = threadIdx.x;
    const int p0  = blockIdx.x * NPIX;

    {
        const float4* wt4 = reinterpret_cast<const float4*>(g_Wt + t * CHN * CHN);
        float4* ws4 = reinterpret_cast<float4*>(&Ws[0][0]);
#pragma unroll
        for (int i = 0; i < 4; ++i) ws4[i * 256 + tid] = wt4[i * 256 + tid];
    }
    {
        const float4* xb4 = reinterpret_cast<const float4*>(x + (size_t)b * CHN * HW + p0);
#pragma unroll
        for (int i = 0; i < 8; ++i) {
            int e = i * 256 + tid;
            int c = e >> 5, q = e & 31;
            *reinterpret_cast<float4*>(&Xs[c][q * 4]) = xb4[(size_t)c * (HW / 4) + q];
        }
    }
    __syncthreads();

    const int tx = tid & 31;
    const int ty = tid >> 5;

    u64 acc2[4][4];
#pragma unroll
    for (int a = 0; a < 4; ++a)
#pragma unroll
        for (int p = 0; p < 4; ++p) acc2[a][p] = 0ull;

    // ---- software-pipelined main loop: prefetch k+1 before fmas of k ----
    float4 xv      = *reinterpret_cast<const float4*>(&Xs[0][tx * 4]);
    ulonglong2 w01 = *reinterpret_cast<const ulonglong2*>(&Ws[0][ty * 8]);
    ulonglong2 w23 = *reinterpret_cast<const ulonglong2*>(&Ws[0][ty * 8 + 4]);
#pragma unroll 4
    for (int k = 0; k < 64; ++k) {
        const int kn = (k + 1) & 63;
        float4 nxv      = *reinterpret_cast<const float4*>(&Xs[kn][tx * 4]);
        ulonglong2 nw01 = *reinterpret_cast<const ulonglong2*>(&Ws[kn][ty * 8]);
        ulonglong2 nw23 = *reinterpret_cast<const ulonglong2*>(&Ws[kn][ty * 8 + 4]);

        u64 wp[4] = {w01.x, w01.y, w23.x, w23.y};          // natural out-chan pairs
        u64 xd[4] = {pack2(xv.x, xv.x), pack2(xv.y, xv.y),
                     pack2(xv.z, xv.z), pack2(xv.w, xv.w)};
#pragma unroll
        for (int a = 0; a < 4; ++a)
#pragma unroll
            for (int p = 0; p < 4; ++p)
                fma2(acc2[a][p], wp[a], xd[p]);

        xv = nxv; w01 = nw01; w23 = nw23;
    }

    float* ob = g_qk + (size_t)t * BATCH * CHN * HW + (size_t)b * CHN * HW + p0;
#pragma unroll
    for (int ap = 0; ap < 4; ++ap) {
        float lo[4], hi[4];
#pragma unroll
        for (int p = 0; p < 4; ++p) unpack2(acc2[ap][p], lo[p], hi[p]);
        int o0 = ty * 8 + 2 * ap;
        *reinterpret_cast<float4*>(&ob[(size_t)o0 * HW + tx * 4]) =
            make_float4(lo[0], lo[1], lo[2], lo[3]);
        *reinterpret_cast<float4*>(&ob[(size_t)(o0 + 1) * HW + tx * 4]) =
            make_float4(hi[0], hi[1], hi[2], hi[3]);

        float s = 0.f, ss = 0.f;
#pragma unroll
        for (int p = 0; p < 4; ++p) {
            s  += lo[p] + hi[p];
            ss += lo[p] * lo[p] + hi[p] * hi[p];
        }
#pragma unroll
        for (int m = 16; m > 0; m >>= 1) {
            s  += __shfl_xor_sync(0xffffffffu, s,  m);
            ss += __shfl_xor_sync(0xffffffffu, ss, m);
        }
        if (tx == 0) {
            int g   = ty * 4 + ap;
            int idx = ((t * BATCH + b) * 32 + g) * 512 + blockIdx.x;
            g_psum[idx] = s;
            g_pss[idx]  = ss;
        }
    }
}

// ---------------- K2: finalize stats -> per-channel scale/bias --------------
__global__ void k_stats(const float* __restrict__ gq, const float* __restrict__ bq,
                        const float* __restrict__ gk, const float* __restrict__ bk)
{
    const int id  = blockIdx.x;
    const int tid = threadIdx.x;
    const float* ps = g_psum + (size_t)id * 512;
    const float* pq = g_pss  + (size_t)id * 512;
    float s  = ps[tid] + ps[tid + 256];
    float ss = pq[tid] + pq[tid + 256];
#pragma unroll
    for (int m = 16; m > 0; m >>= 1) {
        s  += __shfl_xor_sync(0xffffffffu, s,  m);
        ss += __shfl_xor_sync(0xffffffffu, ss, m);
    }
    __shared__ float sh[16];
    int w = tid >> 5;
    if ((tid & 31) == 0) { sh[w] = s; sh[8 + w] = ss; }
    __syncthreads();
    if (tid == 0) {
        float S = 0.f, SS = 0.f;
#pragma unroll
        for (int i = 0; i < 8; ++i) { S += sh[i]; SS += sh[8 + i]; }
        const float inv  = 1.0f / 131072.0f;
        float mean = S * inv;
        float var  = SS * inv - mean * mean;
        float rstd = rsqrtf(var + EPSV);
        int t = id >> 8, b = (id >> 5) & 7, g = id & 31;
        const float* ga = t ? gk : gq;
        const float* be = t ? bk : bq;
#pragma unroll
        for (int j = 0; j < 2; ++j) {
            int c = g * 2 + j;
            float sc = rstd * ga[c];
            g_scale[(t * BATCH + b) * CHN + c] = sc;
            g_bias [(t * BATCH + b) * CHN + c] = be[c] - mean * sc;
        }
    }
}

// ---------------- K3: windowed cross-attention + residual -------------------
// 128 threads = 1 window. 8x4 register tiles paired along q (natural smem
// pairs -> zero-cost fma2 operands), software-pipelined loads, 6 blocks/SM.
__global__ __launch_bounds__(128, 6) void k_attn(const float* __restrict__ xlow,
                                                 float* __restrict__ outp)
{
    extern __shared__ float sm[];
    const int wt = threadIdx.x;         // 0..127
    float (*bufA)[68] = reinterpret_cast<float(*)[68]>(sm);          // q -> K_T
    float (*bufK)[68] = reinterpret_cast<float(*)[68]>(sm + 4352);   // k -> P_T

    const int b  = blockIdx.y;
    const int wi = blockIdx.x;
    const int h0 = (wi >> 5) * 8, w0 = (wi & 31) * 8;
    const size_t gb = (size_t)b * CHN * HW;
    const float* qg = g_qk + gb;
    const float* kg = g_qk + (size_t)BATCH * CHN * HW + gb;
    const float* scq = g_scale + b * CHN;
    const float* biq = g_bias  + b * CHN;
    const float* sck = g_scale + (BATCH + b) * CHN;
    const float* bik = g_bias  + (BATCH + b) * CHN;

    // ---- load q,k with folded GroupNorm, channel-major [c][px], float4 ----
#pragma unroll
    for (int i = 0; i < 8; ++i) {
        int e = i * 128 + wt;
        int c = e >> 4, f = e & 15;          // px = 4f..4f+3
        size_t ga = (size_t)c * HW + (size_t)(h0 + (f >> 1)) * 256 + (w0 + (f & 1) * 4);
        float4 qv = *reinterpret_cast<const float4*>(qg + ga);
        float4 kv = *reinterpret_cast<const float4*>(kg + ga);
        float sq = scq[c], bq_ = biq[c];
        float sk = sck[c], bk_ = bik[c];
        *reinterpret_cast<float4*>(&bufA[c][f * 4]) =
            make_float4(qv.x * sq + bq_, qv.y * sq + bq_, qv.z * sq + bq_, qv.w * sq + bq_);
        *reinterpret_cast<float4*>(&bufK[c][f * 4]) =
            make_float4(kv.x * sk + bk_, kv.y * sk + bk_, kv.z * sk + bk_, kv.w * sk + bk_);
    }
    __syncthreads();

    const int tx = wt & 15;    // key/chan-col group (4 cols)
    const int ty = wt >> 4;    // query-row group (8 rows)

    // ---- GEMM1: S[q][k] = sum_c q[c][q]*k[c][k]; q paired, k dup'd --------
    u64 acc[4][4];             // acc[ip][j]: (S[2ip][j], S[2ip+1][j]) of tile
#pragma unroll
    for (int i = 0; i < 4; ++i)
#pragma unroll
        for (int j = 0; j < 4; ++j) acc[i][j] = 0ull;

    {
        ulonglong2 qA = *reinterpret_cast<const ulonglong2*>(&bufA[0][ty * 8]);
        ulonglong2 qB = *reinterpret_cast<const ulonglong2*>(&bufA[0][ty * 8 + 4]);
        float4 kv     = *reinterpret_cast<const float4*>(&bufK[0][tx * 4]);
#pragma unroll 4
        for (int k = 0; k < 64; ++k) {
            const int kn = (k + 1) & 63;
            ulonglong2 nqA = *reinterpret_cast<const ulonglong2*>(&bufA[kn][ty * 8]);
            ulonglong2 nqB = *reinterpret_cast<const ulonglong2*>(&bufA[kn][ty * 8 + 4]);
            float4 nkv     = *reinterpret_cast<const float4*>(&bufK[kn][tx * 4]);

            u64 qp[4] = {qA.x, qA.y, qB.x, qB.y};          // natural q-row pairs
            u64 kd[4] = {pack2(kv.x, kv.x), pack2(kv.y, kv.y),
                         pack2(kv.z, kv.z), pack2(kv.w, kv.w)};
#pragma unroll
            for (int ip = 0; ip < 4; ++ip)
#pragma unroll
                for (int j = 0; j < 4; ++j)
                    fma2(acc[ip][j], qp[ip], kd[j]);

            qA = nqA; qB = nqB; kv = nkv;
        }
    }

    // ---- softmax over key dim (4 local + 16-lane tx group), scale 1/8 ----
    float p[8][4];
#pragma unroll
    for (int ip = 0; ip < 4; ++ip)
#pragma unroll
        for (int j = 0; j < 4; ++j)
            unpack2(acc[ip][j], p[2 * ip][j], p[2 * ip + 1][j]);

#pragma unroll
    for (int i = 0; i < 8; ++i) {
#pragma unroll
        for (int j = 0; j < 4; ++j) p[i][j] *= 0.125f;
        float m = fmaxf(fmaxf(p[i][0], p[i][1]), fmaxf(p[i][2], p[i][3]));
#pragma unroll
        for (int msk = 8; msk > 0; msk >>= 1)
            m = fmaxf(m, __shfl_xor_sync(0xffffffffu, m, msk));
        float r = 0.f;
#pragma unroll
        for (int j = 0; j < 4; ++j) { p[i][j] = __expf(p[i][j] - m); r += p[i][j]; }
#pragma unroll
        for (int msk = 8; msk > 0; msk >>= 1)
            r += __shfl_xor_sync(0xffffffffu, r, msk);
        float inv = __fdividef(1.0f, r);
#pragma unroll
        for (int j = 0; j < 4; ++j) p[i][j] *= inv;
    }
    __syncthreads();   // GEMM1 reads of bufA/bufK complete

    // ---- K_T into bufA (q dead): bufA[px][c] = bufK[c][px] ----
    {
        const int col = wt & 63;
        const int r0  = (wt >> 6) * 32;
#pragma unroll 8
        for (int i = 0; i < 32; ++i) {
            float v = bufK[r0 + i][col];   // row-major read: conflict-free
            bufA[col][r0 + i] = v;         // column write: 4-way
        }
    }
    __syncthreads();   // all K_T reads of bufK done

    // ---- P_T into bufK directly from registers: bufK[k][q] = P[q][k] ----
#pragma unroll
    for (int i = 0; i < 8; ++i)
#pragma unroll
        for (int j = 0; j < 4; ++j)
            bufK[tx * 4 + j][ty * 8 + i] = p[i][j];
    __syncthreads();

    // ---- GEMM2: out[q][c] = sum_kp P_T[kp][q]*K_T[kp][c]; q paired --------
    u64 o2[4][4];              // o2[ip][j]: (out[2ip][j], out[2ip+1][j])
#pragma unroll
    for (int i = 0; i < 4; ++i)
#pragma unroll
        for (int j = 0; j < 4; ++j) o2[i][j] = 0ull;

    {
        ulonglong2 pA = *reinterpret_cast<const ulonglong2*>(&bufK[0][ty * 8]);
        ulonglong2 pB = *reinterpret_cast<const ulonglong2*>(&bufK[0][ty * 8 + 4]);
        float4 kv     = *reinterpret_cast<const float4*>(&bufA[0][tx * 4]);
#pragma unroll 4
        for (int k = 0; k < 64; ++k) {
            const int kn = (k + 1) & 63;
            ulonglong2 npA = *reinterpret_cast<const ulonglong2*>(&bufK[kn][ty * 8]);
            ulonglong2 npB = *reinterpret_cast<const ulonglong2*>(&bufK[kn][ty * 8 + 4]);
            float4 nkv     = *reinterpret_cast<const float4*>(&bufA[kn][tx * 4]);

            u64 pp[4] = {pA.x, pA.y, pB.x, pB.y};
            u64 kd[4] = {pack2(kv.x, kv.x), pack2(kv.y, kv.y),
                         pack2(kv.z, kv.z), pack2(kv.w, kv.w)};
#pragma unroll
            for (int ip = 0; ip < 4; ++ip)
#pragma unroll
                for (int j = 0; j < 4; ++j)
                    fma2(o2[ip][j], pp[ip], kd[j]);

            pA = npA; pB = npB; kv = nkv;
        }
    }

    // ---- epilogue: residual add + direct global stores ----
    // thread owns pixels q = ty*8..+7 (= window row ty), channels tx*4..+3
    const float* xb = xlow + gb;
    float* ob = outp + gb;
#pragma unroll
    for (int j = 0; j < 4; ++j) {
        float qv[8];
#pragma unroll
        for (int ip = 0; ip < 4; ++ip)
            unpack2(o2[ip][j], qv[2 * ip], qv[2 * ip + 1]);
        int c = tx * 4 + j;
        size_t base = (size_t)c * HW + (size_t)(h0 + ty) * 256 + w0;
        float4 r0 = *reinterpret_cast<const float4*>(xb + base);
        float4 r1 = *reinterpret_cast<const float4*>(xb + base + 4);
        *reinterpret_cast<float4*>(ob + base) =
            make_float4(qv[0] + r0.x, qv[1] + r0.y, qv[2] + r0.z, qv[3] + r0.w);
        *reinterpret_cast<float4*>(ob + base + 4) =
            make_float4(qv[4] + r1.x, qv[5] + r1.y, qv[6] + r1.z, qv[7] + r1.w);
    }
}

// ---------------- launch -----------------------------------------------------
extern "C" void kernel_launch(void* const* d_in, const int* in_sizes, int n_in,
                              void* d_out, int out_size)
{
    (void)in_sizes; (void)n_in; (void)out_size;
    const float* x_low  = (const float*)d_in[0];
    const float* x_high = (const float*)d_in[1];
    const float* Wq = (const float*)d_in[2];
    const float* Wk = (const float*)d_in[3];
    const float* gq = (const float*)d_in[4];
    const float* bq = (const float*)d_in[5];
    const float* gk = (const float*)d_in[6];
    const float* bk = (const float*)d_in[7];
    float* out = (float*)d_out;

    const int attn_smem = 2 * 64 * 68 * 4;   // 34816 B per window/block
    cudaFuncSetAttribute(k_attn, cudaFuncAttributeMaxDynamicSharedMemorySize, attn_smem);

    k_wt  <<<2, 256>>>(Wq, Wk);
    k_conv<<<dim3(512, BATCH, 2), 256>>>(x_low, x_high);
    k_stats<<<512, 256>>>(gq, bq, gk, bk);
    k_attn<<<dim3(1024, BATCH), 128, attn_smem>>>(x_low, out);
}

// round 15
// speedup vs baseline: 1.0467x; 1.0062x over previous
#include <cuda_runtime.h>

// Problem constants (B=8, C=64, H=W=256, GROUPS=32, PATCH=8)
#define HW      65536
#define CHN     64
#define BATCH   8
#define NPIX    128           // pixels per conv block
#define EPSV    1e-5f

typedef unsigned long long u64;

// ---- packed f32x2 helpers (sm_103a; ptxas never auto-fuses these) ----------
__device__ __forceinline__ u64 pack2(float lo, float hi) {
    u64 r;
    asm("mov.b64 %0, {%1, %2};" : "=l"(r) : "f"(lo), "f"(hi));
    return r;
}
__device__ __forceinline__ void unpack2(u64 v, float& lo, float& hi) {
    asm("mov.b64 {%0, %1}, %2;" : "=f"(lo), "=f"(hi) : "l"(v));
}
__device__ __forceinline__ void fma2(u64& d, u64 a, u64 b) {
    asm("fma.rn.f32x2 %0, %1, %2, %0;" : "+l"(d) : "l"(a), "l"(b));
}

// ---------------- scratch (device globals; no allocation allowed) ----------
__device__ float g_qk[2u * BATCH * CHN * HW];     // [t][b][c][hw]  (q then k)
__device__ float g_psum[2 * BATCH * 32 * 512];    // per-block partial sums
__device__ float g_pss [2 * BATCH * 32 * 512];    // per-block partial sum-of-squares
__device__ float g_scale[2 * BATCH * CHN];        // GN folded: per (t,b,c) scale
__device__ float g_bias [2 * BATCH * CHN];        // GN folded: per (t,b,c) bias
__device__ float g_Wt[2 * CHN * CHN];             // W transposed: [t][c][o]

// ---------------- K0: transpose weights into scratch ------------------------
__global__ void k_wt(const float* __restrict__ Wq, const float* __restrict__ Wk)
{
    const float* Wm = blockIdx.x ? Wk : Wq;
    float* o = g_Wt + blockIdx.x * CHN * CHN;
    const int tid = threadIdx.x;
#pragma unroll
    for (int i = 0; i < 16; ++i) {
        int e = i * 256 + tid;
        int r = e >> 6, c = e & 63;
        o[c * CHN + r] = Wm[e];
    }
}

// ---------------- K1: 1x1 conv (GEMM, f32x2, prefetched) + stat partials ----
__global__ __launch_bounds__(256, 3) void k_conv(const float* __restrict__ xlow,
                                                 const float* __restrict__ xhigh)
{
    __shared__ float Xs[64][128];   // [c][pixel]  32KB
    __shared__ float Ws[64][64];    // [c][o]      16KB

    const int t   = blockIdx.z;
    const float* x = t ? xhigh : xlow;
    const int b   = blockIdx.y;
    const int tid = threadIdx.x;
    const int p0  = blockIdx.x * NPIX;

    {
        const float4* wt4 = reinterpret_cast<const float4*>(g_Wt + t * CHN * CHN);
        float4* ws4 = reinterpret_cast<float4*>(&Ws[0][0]);
#pragma unroll
        for (int i = 0; i < 4; ++i) ws4[i * 256 + tid] = wt4[i * 256 + tid];
    }
    {
        const float4* xb4 = reinterpret_cast<const float4*>(x + (size_t)b * CHN * HW + p0);
#pragma unroll
        for (int i = 0; i < 8; ++i) {
            int e = i * 256 + tid;
            int c = e >> 5, q = e & 31;
            *reinterpret_cast<float4*>(&Xs[c][q * 4]) = xb4[(size_t)c * (HW / 4) + q];
        }
    }
    __syncthreads();

    const int tx = tid & 31;
    const int ty = tid >> 5;

    u64 acc2[4][4];
#pragma unroll
    for (int a = 0; a < 4; ++a)
#pragma unroll
        for (int p = 0; p < 4; ++p) acc2[a][p] = 0ull;

    // ---- software-pipelined main loop: prefetch k+1 before fmas of k ----
    float4 xv      = *reinterpret_cast<const float4*>(&Xs[0][tx * 4]);
    ulonglong2 w01 = *reinterpret_cast<const ulonglong2*>(&Ws[0][ty * 8]);
    ulonglong2 w23 = *reinterpret_cast<const ulonglong2*>(&Ws[0][ty * 8 + 4]);
#pragma unroll 4
    for (int k = 0; k < 64; ++k) {
        const int kn = (k + 1) & 63;
        float4 nxv      = *reinterpret_cast<const float4*>(&Xs[kn][tx * 4]);
        ulonglong2 nw01 = *reinterpret_cast<const ulonglong2*>(&Ws[kn][ty * 8]);
        ulonglong2 nw23 = *reinterpret_cast<const ulonglong2*>(&Ws[kn][ty * 8 + 4]);

        u64 wp[4] = {w01.x, w01.y, w23.x, w23.y};          // natural out-chan pairs
        u64 xd[4] = {pack2(xv.x, xv.x), pack2(xv.y, xv.y),
                     pack2(xv.z, xv.z), pack2(xv.w, xv.w)};
#pragma unroll
        for (int a = 0; a < 4; ++a)
#pragma unroll
            for (int p = 0; p < 4; ++p)
                fma2(acc2[a][p], wp[a], xd[p]);

        xv = nxv; w01 = nw01; w23 = nw23;
    }

    float* ob = g_qk + (size_t)t * BATCH * CHN * HW + (size_t)b * CHN * HW + p0;
#pragma unroll
    for (int ap = 0; ap < 4; ++ap) {
        float lo[4], hi[4];
#pragma unroll
        for (int p = 0; p < 4; ++p) unpack2(acc2[ap][p], lo[p], hi[p]);
        int o0 = ty * 8 + 2 * ap;
        *reinterpret_cast<float4*>(&ob[(size_t)o0 * HW + tx * 4]) =
            make_float4(lo[0], lo[1], lo[2], lo[3]);
        *reinterpret_cast<float4*>(&ob[(size_t)(o0 + 1) * HW + tx * 4]) =
            make_float4(hi[0], hi[1], hi[2], hi[3]);

        float s = 0.f, ss = 0.f;
#pragma unroll
        for (int p = 0; p < 4; ++p) {
            s  += lo[p] + hi[p];
            ss += lo[p] * lo[p] + hi[p] * hi[p];
        }
#pragma unroll
        for (int m = 16; m > 0; m >>= 1) {
            s  += __shfl_xor_sync(0xffffffffu, s,  m);
            ss += __shfl_xor_sync(0xffffffffu, ss, m);
        }
        if (tx == 0) {
            int g   = ty * 4 + ap;
            int idx = ((t * BATCH + b) * 32 + g) * 512 + blockIdx.x;
            g_psum[idx] = s;
            g_pss[idx]  = ss;
        }
    }
}

// ---------------- K2: finalize stats -> per-channel scale/bias --------------
__global__ void k_stats(const float* __restrict__ gq, const float* __restrict__ bq,
                        const float* __restrict__ gk, const float* __restrict__ bk)
{
    const int id  = blockIdx.x;
    const int tid = threadIdx.x;
    const float* ps = g_psum + (size_t)id * 512;
    const float* pq = g_pss  + (size_t)id * 512;
    float s  = ps[tid] + ps[tid + 256];
    float ss = pq[tid] + pq[tid + 256];
#pragma unroll
    for (int m = 16; m > 0; m >>= 1) {
        s  += __shfl_xor_sync(0xffffffffu, s,  m);
        ss += __shfl_xor_sync(0xffffffffu, ss, m);
    }
    __shared__ float sh[16];
    int w = tid >> 5;
    if ((tid & 31) == 0) { sh[w] = s; sh[8 + w] = ss; }
    __syncthreads();
    if (tid == 0) {
        float S = 0.f, SS = 0.f;
#pragma unroll
        for (int i = 0; i < 8; ++i) { S += sh[i]; SS += sh[8 + i]; }
        const float inv  = 1.0f / 131072.0f;
        float mean = S * inv;
        float var  = SS * inv - mean * mean;
        float rstd = rsqrtf(var + EPSV);
        int t = id >> 8, b = (id >> 5) & 7, g = id & 31;
        const float* ga = t ? gk : gq;
        const float* be = t ? bk : bq;
#pragma unroll
        for (int j = 0; j < 2; ++j) {
            int c = g * 2 + j;
            float sc = rstd * ga[c];
            g_scale[(t * BATCH + b) * CHN + c] = sc;
            g_bias [(t * BATCH + b) * CHN + c] = be[c] - mean * sc;
        }
    }
}

// ---------------- K3: windowed cross-attention + residual -------------------
// 128 threads = 1 window. 8x4 register tiles paired along q (natural smem
// pairs -> zero-cost fma2 operands), software-pipelined loads, 6 blocks/SM.
__global__ __launch_bounds__(128, 6) void k_attn(const float* __restrict__ xlow,
                                                 float* __restrict__ outp)
{
    extern __shared__ float sm[];
    const int wt = threadIdx.x;         // 0..127
    float (*bufA)[68] = reinterpret_cast<float(*)[68]>(sm);          // q -> K_T
    float (*bufK)[68] = reinterpret_cast<float(*)[68]>(sm + 4352);   // k -> P_T

    const int b  = blockIdx.y;
    const int wi = blockIdx.x;
    const int h0 = (wi >> 5) * 8, w0 = (wi & 31) * 8;
    const size_t gb = (size_t)b * CHN * HW;
    const float* qg = g_qk + gb;
    const float* kg = g_qk + (size_t)BATCH * CHN * HW + gb;
    const float* scq = g_scale + b * CHN;
    const float* biq = g_bias  + b * CHN;
    const float* sck = g_scale + (BATCH + b) * CHN;
    const float* bik = g_bias  + (BATCH + b) * CHN;

    // ---- load q,k with folded GroupNorm, channel-major [c][px], float4 ----
#pragma unroll
    for (int i = 0; i < 8; ++i) {
        int e = i * 128 + wt;
        int c = e >> 4, f = e & 15;          // px = 4f..4f+3
        size_t ga = (size_t)c * HW + (size_t)(h0 + (f >> 1)) * 256 + (w0 + (f & 1) * 4);
        float4 qv = *reinterpret_cast<const float4*>(qg + ga);
        float4 kv = *reinterpret_cast<const float4*>(kg + ga);
        float sq = scq[c], bq_ = biq[c];
        float sk = sck[c], bk_ = bik[c];
        *reinterpret_cast<float4*>(&bufA[c][f * 4]) =
            make_float4(qv.x * sq + bq_, qv.y * sq + bq_, qv.z * sq + bq_, qv.w * sq + bq_);
        *reinterpret_cast<float4*>(&bufK[c][f * 4]) =
            make_float4(kv.x * sk + bk_, kv.y * sk + bk_, kv.z * sk + bk_, kv.w * sk + bk_);
    }
    __syncthreads();

    const int tx = wt & 15;    // key/chan-col group (4 cols)
    const int ty = wt >> 4;    // query-row group (8 rows)

    // ---- GEMM1: S[q][k] = sum_c q[c][q]*k[c][k]; q paired, k dup'd --------
    u64 acc[4][4];             // acc[ip][j]: (S[2ip][j], S[2ip+1][j]) of tile
#pragma unroll
    for (int i = 0; i < 4; ++i)
#pragma unroll
        for (int j = 0; j < 4; ++j) acc[i][j] = 0ull;

    {
        ulonglong2 qA = *reinterpret_cast<const ulonglong2*>(&bufA[0][ty * 8]);
        ulonglong2 qB = *reinterpret_cast<const ulonglong2*>(&bufA[0][ty * 8 + 4]);
        float4 kv     = *reinterpret_cast<const float4*>(&bufK[0][tx * 4]);
#pragma unroll 4
        for (int k = 0; k < 64; ++k) {
            const int kn = (k + 1) & 63;
            ulonglong2 nqA = *reinterpret_cast<const ulonglong2*>(&bufA[kn][ty * 8]);
            ulonglong2 nqB = *reinterpret_cast<const ulonglong2*>(&bufA[kn][ty * 8 + 4]);
            float4 nkv     = *reinterpret_cast<const float4*>(&bufK[kn][tx * 4]);

            u64 qp[4] = {qA.x, qA.y, qB.x, qB.y};          // natural q-row pairs
            u64 kd[4] = {pack2(kv.x, kv.x), pack2(kv.y, kv.y),
                         pack2(kv.z, kv.z), pack2(kv.w, kv.w)};
#pragma unroll
            for (int ip = 0; ip < 4; ++ip)
#pragma unroll
                for (int j = 0; j < 4; ++j)
                    fma2(acc[ip][j], qp[ip], kd[j]);

            qA = nqA; qB = nqB; kv = nkv;
        }
    }

    // ---- softmax over key dim (4 local + 16-lane tx group), scale 1/8 ----
    float p[8][4];
#pragma unroll
    for (int ip = 0; ip < 4; ++ip)
#pragma unroll
        for (int j = 0; j < 4; ++j)
            unpack2(acc[ip][j], p[2 * ip][j], p[2 * ip + 1][j]);

#pragma unroll
    for (int i = 0; i < 8; ++i) {
#pragma unroll
        for (int j = 0; j < 4; ++j) p[i][j] *= 0.125f;
        float m = fmaxf(fmaxf(p[i][0], p[i][1]), fmaxf(p[i][2], p[i][3]));
#pragma unroll
        for (int msk = 8; msk > 0; msk >>= 1)
            m = fmaxf(m, __shfl_xor_sync(0xffffffffu, m, msk));
        float r = 0.f;
#pragma unroll
        for (int j = 0; j < 4; ++j) { p[i][j] = __expf(p[i][j] - m); r += p[i][j]; }
#pragma unroll
        for (int msk = 8; msk > 0; msk >>= 1)
            r += __shfl_xor_sync(0xffffffffu, r, msk);
        float inv = __fdividef(1.0f, r);
#pragma unroll
        for (int j = 0; j < 4; ++j) p[i][j] *= inv;
    }
    __syncthreads();   // GEMM1 reads of bufA/bufK complete

    // ---- K_T into bufA (q dead): bufA[px][c] = bufK[c][px] ----
    {
        const int col = wt & 63;
        const int r0  = (wt >> 6) * 32;
#pragma unroll 8
        for (int i = 0; i < 32; ++i) {
            float v = bufK[r0 + i][col];   // row-major read: conflict-free
            bufA[col][r0 + i] = v;         // column write: 4-way
        }
    }
    __syncthreads();   // all K_T reads of bufK done

    // ---- P_T into bufK directly from registers: bufK[k][q] = P[q][k] ----
#pragma unroll
    for (int i = 0; i < 8; ++i)
#pragma unroll
        for (int j = 0; j < 4; ++j)
            bufK[tx * 4 + j][ty * 8 + i] = p[i][j];
    __syncthreads();

    // ---- GEMM2: out[q][c] = sum_kp P_T[kp][q]*K_T[kp][c]; q paired --------
    u64 o2[4][4];              // o2[ip][j]: (out[2ip][j], out[2ip+1][j])
#pragma unroll
    for (int i = 0; i < 4; ++i)
#pragma unroll
        for (int j = 0; j < 4; ++j) o2[i][j] = 0ull;

    {
        ulonglong2 pA = *reinterpret_cast<const ulonglong2*>(&bufK[0][ty * 8]);
        ulonglong2 pB = *reinterpret_cast<const ulonglong2*>(&bufK[0][ty * 8 + 4]);
        float4 kv     = *reinterpret_cast<const float4*>(&bufA[0][tx * 4]);
#pragma unroll 4
        for (int k = 0; k < 64; ++k) {
            const int kn = (k + 1) & 63;
            ulonglong2 npA = *reinterpret_cast<const ulonglong2*>(&bufK[kn][ty * 8]);
            ulonglong2 npB = *reinterpret_cast<const ulonglong2*>(&bufK[kn][ty * 8 + 4]);
            float4 nkv     = *reinterpret_cast<const float4*>(&bufA[kn][tx * 4]);

            u64 pp[4] = {pA.x, pA.y, pB.x, pB.y};
            u64 kd[4] = {pack2(kv.x, kv.x), pack2(kv.y, kv.y),
                         pack2(kv.z, kv.z), pack2(kv.w, kv.w)};
#pragma unroll
            for (int ip = 0; ip < 4; ++ip)
#pragma unroll
                for (int j = 0; j < 4; ++j)
                    fma2(o2[ip][j], pp[ip], kd[j]);

            pA = npA; pB = npB; kv = nkv;
        }
    }

    // ---- epilogue: residual add + direct global stores ----
    // thread owns pixels q = ty*8..+7 (= window row ty), channels tx*4..+3
    const float* xb = xlow + gb;
    float* ob = outp + gb;
#pragma unroll
    for (int j = 0; j < 4; ++j) {
        float qv[8];
#pragma unroll
        for (int ip = 0; ip < 4; ++ip)
            unpack2(o2[ip][j], qv[2 * ip], qv[2 * ip + 1]);
        int c = tx * 4 + j;
        size_t base = (size_t)c * HW + (size_t)(h0 + ty) * 256 + w0;
        float4 r0 = *reinterpret_cast<const float4*>(xb + base);
        float4 r1 = *reinterpret_cast<const float4*>(xb + base + 4);
        *reinterpret_cast<float4*>(ob + base) =
            make_float4(qv[0] + r0.x, qv[1] + r0.y, qv[2] + r0.z, qv[3] + r0.w);
        *reinterpret_cast<float4*>(ob + base + 4) =
            make_float4(qv[4] + r1.x, qv[5] + r1.y, qv[6] + r1.z, qv[7] + r1.w);
    }
}

// ---------------- launch -----------------------------------------------------
extern "C" void kernel_launch(void* const* d_in, const int* in_sizes, int n_in,
                              void* d_out, int out_size)
{
    (void)in_sizes; (void)n_in; (void)out_size;
    const float* x_low  = (const float*)d_in[0];
    const float* x_high = (const float*)d_in[1];
    const float* Wq = (const float*)d_in[2];
    const float* Wk = (const float*)d_in[3];
    const float* gq = (const float*)d_in[4];
    const float* bq = (const float*)d_in[5];
    const float* gk = (const float*)d_in[6];
    const float* bk = (const float*)d_in[7];
    float* out = (float*)d_out;

    const int attn_smem = 2 * 64 * 68 * 4;   // 34816 B per window/block
    cudaFuncSetAttribute(k_attn, cudaFuncAttributeMaxDynamicSharedMemorySize, attn_smem);

    k_wt  <<<2, 256>>>(Wq, Wk);
    k_conv<<<dim3(512, BATCH, 2), 256>>>(x_low, x_high);
    k_stats<<<512, 256>>>(gq, bq, gk, bk);
    k_attn<<<dim3(1024, BATCH), 128, attn_smem>>>(x_low, out);
}

// round 16
// speedup vs baseline: 1.0469x; 1.0002x over previous
#include <cuda_runtime.h>

// Problem constants (B=8, C=64, H=W=256, GROUPS=32, PATCH=8)
#define HW      65536
#define CHN     64
#define BATCH   8
#define NPIX    128           // pixels per conv block
#define EPSV    1e-5f

typedef unsigned long long u64;

// ---- packed f32x2 helpers (sm_103a; ptxas never auto-fuses these) ----------
__device__ __forceinline__ u64 pack2(float lo, float hi) {
    u64 r;
    asm("mov.b64 %0, {%1, %2};" : "=l"(r) : "f"(lo), "f"(hi));
    return r;
}
__device__ __forceinline__ void unpack2(u64 v, float& lo, float& hi) {
    asm("mov.b64 {%0, %1}, %2;" : "=f"(lo), "=f"(hi) : "l"(v));
}
__device__ __forceinline__ void fma2(u64& d, u64 a, u64 b) {
    asm("fma.rn.f32x2 %0, %1, %2, %0;" : "+l"(d) : "l"(a), "l"(b));
}

// ---------------- scratch (device globals; no allocation allowed) ----------
__device__ float g_qk[2u * BATCH * CHN * HW];     // [t][b][c][hw]  (q then k)
__device__ float g_psum[2 * BATCH * 32 * 512];    // per-block partial sums
__device__ float g_pss [2 * BATCH * 32 * 512];    // per-block partial sum-of-squares
__device__ float g_scale[2 * BATCH * CHN];        // GN folded: per (t,b,c) scale
__device__ float g_bias [2 * BATCH * CHN];        // GN folded: per (t,b,c) bias
__device__ float g_Wt[2 * CHN * CHN];             // W transposed: [t][c][o]

// ---------------- K0: transpose weights into scratch ------------------------
__global__ void k_wt(const float* __restrict__ Wq, const float* __restrict__ Wk)
{
    const float* Wm = blockIdx.x ? Wk : Wq;
    float* o = g_Wt + blockIdx.x * CHN * CHN;
    const int tid = threadIdx.x;
#pragma unroll
    for (int i = 0; i < 16; ++i) {
        int e = i * 256 + tid;
        int r = e >> 6, c = e & 63;
        o[c * CHN + r] = Wm[e];
    }
}

// ---------------- K1: 1x1 conv (GEMM, f32x2, prefetched) + stat partials ----
__global__ __launch_bounds__(256, 3) void k_conv(const float* __restrict__ xlow,
                                                 const float* __restrict__ xhigh)
{
    __shared__ float Xs[64][128];   // [c][pixel]  32KB
    __shared__ float Ws[64][64];    // [c][o]      16KB

    const int t   = blockIdx.z;
    const float* x = t ? xhigh : xlow;
    const int b   = blockIdx.y;
    const int tid = threadIdx.x;
    const int p0  = blockIdx.x * NPIX;

    {
        const float4* wt4 = reinterpret_cast<const float4*>(g_Wt + t * CHN * CHN);
        float4* ws4 = reinterpret_cast<float4*>(&Ws[0][0]);
#pragma unroll
        for (int i = 0; i < 4; ++i) ws4[i * 256 + tid] = wt4[i * 256 + tid];
    }
    {
        const float4* xb4 = reinterpret_cast<const float4*>(x + (size_t)b * CHN * HW + p0);
#pragma unroll
        for (int i = 0; i < 8; ++i) {
            int e = i * 256 + tid;
            int c = e >> 5, q = e & 31;
            *reinterpret_cast<float4*>(&Xs[c][q * 4]) = xb4[(size_t)c * (HW / 4) + q];
        }
    }
    __syncthreads();

    const int tx = tid & 31;
    const int ty = tid >> 5;

    u64 acc2[4][4];
#pragma unroll
    for (int a = 0; a < 4; ++a)
#pragma unroll
        for (int p = 0; p < 4; ++p) acc2[a][p] = 0ull;

    // ---- software-pipelined main loop: prefetch k+1 before fmas of k ----
    float4 xv      = *reinterpret_cast<const float4*>(&Xs[0][tx * 4]);
    ulonglong2 w01 = *reinterpret_cast<const ulonglong2*>(&Ws[0][ty * 8]);
    ulonglong2 w23 = *reinterpret_cast<const ulonglong2*>(&Ws[0][ty * 8 + 4]);
#pragma unroll 4
    for (int k = 0; k < 64; ++k) {
        const int kn = (k + 1) & 63;
        float4 nxv      = *reinterpret_cast<const float4*>(&Xs[kn][tx * 4]);
        ulonglong2 nw01 = *reinterpret_cast<const ulonglong2*>(&Ws[kn][ty * 8]);
        ulonglong2 nw23 = *reinterpret_cast<const ulonglong2*>(&Ws[kn][ty * 8 + 4]);

        u64 wp[4] = {w01.x, w01.y, w23.x, w23.y};          // natural out-chan pairs
        u64 xd[4] = {pack2(xv.x, xv.x), pack2(xv.y, xv.y),
                     pack2(xv.z, xv.z), pack2(xv.w, xv.w)};
#pragma unroll
        for (int a = 0; a < 4; ++a)
#pragma unroll
            for (int p = 0; p < 4; ++p)
                fma2(acc2[a][p], wp[a], xd[p]);

        xv = nxv; w01 = nw01; w23 = nw23;
    }

    float* ob = g_qk + (size_t)t * BATCH * CHN * HW + (size_t)b * CHN * HW + p0;
#pragma unroll
    for (int ap = 0; ap < 4; ++ap) {
        float lo[4], hi[4];
#pragma unroll
        for (int p = 0; p < 4; ++p) unpack2(acc2[ap][p], lo[p], hi[p]);
        int o0 = ty * 8 + 2 * ap;
        *reinterpret_cast<float4*>(&ob[(size_t)o0 * HW + tx * 4]) =
            make_float4(lo[0], lo[1], lo[2], lo[3]);
        *reinterpret_cast<float4*>(&ob[(size_t)(o0 + 1) * HW + tx * 4]) =
            make_float4(hi[0], hi[1], hi[2], hi[3]);

        float s = 0.f, ss = 0.f;
#pragma unroll
        for (int p = 0; p < 4; ++p) {
            s  += lo[p] + hi[p];
            ss += lo[p] * lo[p] + hi[p] * hi[p];
        }
#pragma unroll
        for (int m = 16; m > 0; m >>= 1) {
            s  += __shfl_xor_sync(0xffffffffu, s,  m);
            ss += __shfl_xor_sync(0xffffffffu, ss, m);
        }
        if (tx == 0) {
            int g   = ty * 4 + ap;
            int idx = ((t * BATCH + b) * 32 + g) * 512 + blockIdx.x;
            g_psum[idx] = s;
            g_pss[idx]  = ss;
        }
    }
}

// ---------------- K2: finalize stats -> per-channel scale/bias --------------
__global__ void k_stats(const float* __restrict__ gq, const float* __restrict__ bq,
                        const float* __restrict__ gk, const float* __restrict__ bk)
{
    const int id  = blockIdx.x;
    const int tid = threadIdx.x;
    const float* ps = g_psum + (size_t)id * 512;
    const float* pq = g_pss  + (size_t)id * 512;
    float s  = ps[tid] + ps[tid + 256];
    float ss = pq[tid] + pq[tid + 256];
#pragma unroll
    for (int m = 16; m > 0; m >>= 1) {
        s  += __shfl_xor_sync(0xffffffffu, s,  m);
        ss += __shfl_xor_sync(0xffffffffu, ss, m);
    }
    __shared__ float sh[16];
    int w = tid >> 5;
    if ((tid & 31) == 0) { sh[w] = s; sh[8 + w] = ss; }
    __syncthreads();
    if (tid == 0) {
        float S = 0.f, SS = 0.f;
#pragma unroll
        for (int i = 0; i < 8; ++i) { S += sh[i]; SS += sh[8 + i]; }
        const float inv  = 1.0f / 131072.0f;
        float mean = S * inv;
        float var  = SS * inv - mean * mean;
        float rstd = rsqrtf(var + EPSV);
        int t = id >> 8, b = (id >> 5) & 7, g = id & 31;
        const float* ga = t ? gk : gq;
        const float* be = t ? bk : bq;
#pragma unroll
        for (int j = 0; j < 2; ++j) {
            int c = g * 2 + j;
            float sc = rstd * ga[c];
            g_scale[(t * BATCH + b) * CHN + c] = sc;
            g_bias [(t * BATCH + b) * CHN + c] = be[c] - mean * sc;
        }
    }
}

// ---------------- K3: windowed cross-attention + residual -------------------
// 128 threads = 1 window. 8x4 register tiles paired along q (natural smem
// pairs -> zero-cost fma2 operands), software-pipelined loads, 6 blocks/SM.
__global__ __launch_bounds__(128, 6) void k_attn(const float* __restrict__ xlow,
                                                 float* __restrict__ outp)
{
    extern __shared__ float sm[];
    const int wt = threadIdx.x;         // 0..127
    float (*bufA)[68] = reinterpret_cast<float(*)[68]>(sm);          // q -> K_T
    float (*bufK)[68] = reinterpret_cast<float(*)[68]>(sm + 4352);   // k -> P_T

    const int b  = blockIdx.y;
    const int wi = blockIdx.x;
    const int h0 = (wi >> 5) * 8, w0 = (wi & 31) * 8;
    const size_t gb = (size_t)b * CHN * HW;
    const float* qg = g_qk + gb;
    const float* kg = g_qk + (size_t)BATCH * CHN * HW + gb;
    const float* scq = g_scale + b * CHN;
    const float* biq = g_bias  + b * CHN;
    const float* sck = g_scale + (BATCH + b) * CHN;
    const float* bik = g_bias  + (BATCH + b) * CHN;

    // ---- load q,k with folded GroupNorm, channel-major [c][px], float4 ----
#pragma unroll
    for (int i = 0; i < 8; ++i) {
        int e = i * 128 + wt;
        int c = e >> 4, f = e & 15;          // px = 4f..4f+3
        size_t ga = (size_t)c * HW + (size_t)(h0 + (f >> 1)) * 256 + (w0 + (f & 1) * 4);
        float4 qv = *reinterpret_cast<const float4*>(qg + ga);
        float4 kv = *reinterpret_cast<const float4*>(kg + ga);
        float sq = scq[c], bq_ = biq[c];
        float sk = sck[c], bk_ = bik[c];
        *reinterpret_cast<float4*>(&bufA[c][f * 4]) =
            make_float4(qv.x * sq + bq_, qv.y * sq + bq_, qv.z * sq + bq_, qv.w * sq + bq_);
        *reinterpret_cast<float4*>(&bufK[c][f * 4]) =
            make_float4(kv.x * sk + bk_, kv.y * sk + bk_, kv.z * sk + bk_, kv.w * sk + bk_);
    }
    __syncthreads();

    const int tx = wt & 15;    // key/chan-col group (4 cols)
    const int ty = wt >> 4;    // query-row group (8 rows)

    // ---- GEMM1: S[q][k] = sum_c q[c][q]*k[c][k]; q paired, k dup'd --------
    u64 acc[4][4];             // acc[ip][j]: (S[2ip][j], S[2ip+1][j]) of tile
#pragma unroll
    for (int i = 0; i < 4; ++i)
#pragma unroll
        for (int j = 0; j < 4; ++j) acc[i][j] = 0ull;

    {
        ulonglong2 qA = *reinterpret_cast<const ulonglong2*>(&bufA[0][ty * 8]);
        ulonglong2 qB = *reinterpret_cast<const ulonglong2*>(&bufA[0][ty * 8 + 4]);
        float4 kv     = *reinterpret_cast<const float4*>(&bufK[0][tx * 4]);
#pragma unroll 4
        for (int k = 0; k < 64; ++k) {
            const int kn = (k + 1) & 63;
            ulonglong2 nqA = *reinterpret_cast<const ulonglong2*>(&bufA[kn][ty * 8]);
            ulonglong2 nqB = *reinterpret_cast<const ulonglong2*>(&bufA[kn][ty * 8 + 4]);
            float4 nkv     = *reinterpret_cast<const float4*>(&bufK[kn][tx * 4]);

            u64 qp[4] = {qA.x, qA.y, qB.x, qB.y};          // natural q-row pairs
            u64 kd[4] = {pack2(kv.x, kv.x), pack2(kv.y, kv.y),
                         pack2(kv.z, kv.z), pack2(kv.w, kv.w)};
#pragma unroll
            for (int ip = 0; ip < 4; ++ip)
#pragma unroll
                for (int j = 0; j < 4; ++j)
                    fma2(acc[ip][j], qp[ip], kd[j]);

            qA = nqA; qB = nqB; kv = nkv;
        }
    }

    // ---- softmax over key dim (4 local + 16-lane tx group), scale 1/8 ----
    float p[8][4];
#pragma unroll
    for (int ip = 0; ip < 4; ++ip)
#pragma unroll
        for (int j = 0; j < 4; ++j)
            unpack2(acc[ip][j], p[2 * ip][j], p[2 * ip + 1][j]);

#pragma unroll
    for (int i = 0; i < 8; ++i) {
#pragma unroll
        for (int j = 0; j < 4; ++j) p[i][j] *= 0.125f;
        float m = fmaxf(fmaxf(p[i][0], p[i][1]), fmaxf(p[i][2], p[i][3]));
#pragma unroll
        for (int msk = 8; msk > 0; msk >>= 1)
            m = fmaxf(m, __shfl_xor_sync(0xffffffffu, m, msk));
        float r = 0.f;
#pragma unroll
        for (int j = 0; j < 4; ++j) { p[i][j] = __expf(p[i][j] - m); r += p[i][j]; }
#pragma unroll
        for (int msk = 8; msk > 0; msk >>= 1)
            r += __shfl_xor_sync(0xffffffffu, r, msk);
        float inv = __fdividef(1.0f, r);
#pragma unroll
        for (int j = 0; j < 4; ++j) p[i][j] *= inv;
    }
    __syncthreads();   // GEMM1 reads of bufA/bufK complete

    // ---- K_T into bufA (q dead): bufA[px][c] = bufK[c][px] ----
    {
        const int col = wt & 63;
        const int r0  = (wt >> 6) * 32;
#pragma unroll 8
        for (int i = 0; i < 32; ++i) {
            float v = bufK[r0 + i][col];   // row-major read: conflict-free
            bufA[col][r0 + i] = v;         // column write: 4-way
        }
    }
    __syncthreads();   // all K_T reads of bufK done

    // ---- P_T into bufK directly from registers: bufK[k][q] = P[q][k] ----
#pragma unroll
    for (int i = 0; i < 8; ++i)
#pragma unroll
        for (int j = 0; j < 4; ++j)
            bufK[tx * 4 + j][ty * 8 + i] = p[i][j];
    __syncthreads();

    // ---- GEMM2: out[q][c] = sum_kp P_T[kp][q]*K_T[kp][c]; q paired --------
    u64 o2[4][4];              // o2[ip][j]: (out[2ip][j], out[2ip+1][j])
#pragma unroll
    for (int i = 0; i < 4; ++i)
#pragma unroll
        for (int j = 0; j < 4; ++j) o2[i][j] = 0ull;

    {
        ulonglong2 pA = *reinterpret_cast<const ulonglong2*>(&bufK[0][ty * 8]);
        ulonglong2 pB = *reinterpret_cast<const ulonglong2*>(&bufK[0][ty * 8 + 4]);
        float4 kv     = *reinterpret_cast<const float4*>(&bufA[0][tx * 4]);
#pragma unroll 4
        for (int k = 0; k < 64; ++k) {
            const int kn = (k + 1) & 63;
            ulonglong2 npA = *reinterpret_cast<const ulonglong2*>(&bufK[kn][ty * 8]);
            ulonglong2 npB = *reinterpret_cast<const ulonglong2*>(&bufK[kn][ty * 8 + 4]);
            float4 nkv     = *reinterpret_cast<const float4*>(&bufA[kn][tx * 4]);

            u64 pp[4] = {pA.x, pA.y, pB.x, pB.y};
            u64 kd[4] = {pack2(kv.x, kv.x), pack2(kv.y, kv.y),
                         pack2(kv.z, kv.z), pack2(kv.w, kv.w)};
#pragma unroll
            for (int ip = 0; ip < 4; ++ip)
#pragma unroll
                for (int j = 0; j < 4; ++j)
                    fma2(o2[ip][j], pp[ip], kd[j]);

            pA = npA; pB = npB; kv = nkv;
        }
    }

    // ---- epilogue: residual add + direct global stores ----
    // thread owns pixels q = ty*8..+7 (= window row ty), channels tx*4..+3
    const float* xb = xlow + gb;
    float* ob = outp + gb;
#pragma unroll
    for (int j = 0; j < 4; ++j) {
        float qv[8];
#pragma unroll
        for (int ip = 0; ip < 4; ++ip)
            unpack2(o2[ip][j], qv[2 * ip], qv[2 * ip + 1]);
        int c = tx * 4 + j;
        size_t base = (size_t)c * HW + (size_t)(h0 + ty) * 256 + w0;
        float4 r0 = *reinterpret_cast<const float4*>(xb + base);
        float4 r1 = *reinterpret_cast<const float4*>(xb + base + 4);
        *reinterpret_cast<float4*>(ob + base) =
            make_float4(qv[0] + r0.x, qv[1] + r0.y, qv[2] + r0.z, qv[3] + r0.w);
        *reinterpret_cast<float4*>(ob + base + 4) =
            make_float4(qv[4] + r1.x, qv[5] + r1.y, qv[6] + r1.z, qv[7] + r1.w);
    }
}

// ---------------- launch -----------------------------------------------------
extern "C" void kernel_launch(void* const* d_in, const int* in_sizes, int n_in,
                              void* d_out, int out_size)
{
    (void)in_sizes; (void)n_in; (void)out_size;
    const float* x_low  = (const float*)d_in[0];
    const float* x_high = (const float*)d_in[1];
    const float* Wq = (const float*)d_in[2];
    const float* Wk = (const float*)d_in[3];
    const float* gq = (const float*)d_in[4];
    const float* bq = (const float*)d_in[5];
    const float* gk = (const float*)d_in[6];
    const float* bk = (const float*)d_in[7];
    float* out = (float*)d_out;

    const int attn_smem = 2 * 64 * 68 * 4;   // 34816 B per window/block
    cudaFuncSetAttribute(k_attn, cudaFuncAttributeMaxDynamicSharedMemorySize, attn_smem);

    k_wt  <<<2, 256>>>(Wq, Wk);
    k_conv<<<dim3(512, BATCH, 2), 256>>>(x_low, x_high);
    k_stats<<<512, 256>>>(gq, bq, gk, bk);
    k_attn<<<dim3(1024, BATCH), 128, attn_smem>>>(x_low, out);
}

// round 17
// speedup vs baseline: 1.0491x; 1.0021x over previous
#include <cuda_runtime.h>

// Problem constants (B=8, C=64, H=W=256, GROUPS=32, PATCH=8)
#define HW      65536
#define CHN     64
#define BATCH   8
#define NPIX    128           // pixels per conv block
#define EPSV    1e-5f

typedef unsigned long long u64;

// ---- packed f32x2 helpers (sm_103a; ptxas never auto-fuses these) ----------
__device__ __forceinline__ u64 pack2(float lo, float hi) {
    u64 r;
    asm("mov.b64 %0, {%1, %2};" : "=l"(r) : "f"(lo), "f"(hi));
    return r;
}
__device__ __forceinline__ void unpack2(u64 v, float& lo, float& hi) {
    asm("mov.b64 {%0, %1}, %2;" : "=f"(lo), "=f"(hi) : "l"(v));
}
__device__ __forceinline__ void fma2(u64& d, u64 a, u64 b) {
    asm("fma.rn.f32x2 %0, %1, %2, %0;" : "+l"(d) : "l"(a), "l"(b));
}

// ---------------- scratch (device globals; no allocation allowed) ----------
__device__ float g_qk[2u * BATCH * CHN * HW];     // [t][b][c][hw]  (q then k)
__device__ float g_psum[2 * BATCH * 32 * 512];    // per-block partial sums
__device__ float g_pss [2 * BATCH * 32 * 512];    // per-block partial sum-of-squares
__device__ float g_scale[2 * BATCH * CHN];        // GN folded: per (t,b,c) scale
__device__ float g_bias [2 * BATCH * CHN];        // GN folded: per (t,b,c) bias
__device__ float g_Wt[2 * CHN * CHN];             // W transposed: [t][c][o]

// ---------------- K0: transpose weights into scratch ------------------------
__global__ void k_wt(const float* __restrict__ Wq, const float* __restrict__ Wk)
{
    const float* Wm = blockIdx.x ? Wk : Wq;
    float* o = g_Wt + blockIdx.x * CHN * CHN;
    const int tid = threadIdx.x;
#pragma unroll
    for (int i = 0; i < 16; ++i) {
        int e = i * 256 + tid;
        int r = e >> 6, c = e & 63;
        o[c * CHN + r] = Wm[e];
    }
}

// ---------------- K1: 1x1 conv (GEMM, f32x2, prefetched) + stat partials ----
__global__ __launch_bounds__(256, 3) void k_conv(const float* __restrict__ xlow,
                                                 const float* __restrict__ xhigh)
{
    __shared__ float Xs[64][128];   // [c][pixel]  32KB
    __shared__ float Ws[64][64];    // [c][o]      16KB

    const int t   = blockIdx.z;
    const float* x = t ? xhigh : xlow;
    const int b   = blockIdx.y;
    const int tid = threadIdx.x;
    const int p0  = blockIdx.x * NPIX;

    {
        const float4* wt4 = reinterpret_cast<const float4*>(g_Wt + t * CHN * CHN);
        float4* ws4 = reinterpret_cast<float4*>(&Ws[0][0]);
#pragma unroll
        for (int i = 0; i < 4; ++i) ws4[i * 256 + tid] = wt4[i * 256 + tid];
    }
    {
        const float4* xb4 = reinterpret_cast<const float4*>(x + (size_t)b * CHN * HW + p0);
#pragma unroll
        for (int i = 0; i < 8; ++i) {
            int e = i * 256 + tid;
            int c = e >> 5, q = e & 31;
            *reinterpret_cast<float4*>(&Xs[c][q * 4]) = xb4[(size_t)c * (HW / 4) + q];
        }
    }
    __syncthreads();

    const int tx = tid & 31;
    const int ty = tid >> 5;

    u64 acc2[4][4];
#pragma unroll
    for (int a = 0; a < 4; ++a)
#pragma unroll
        for (int p = 0; p < 4; ++p) acc2[a][p] = 0ull;

    // ---- software-pipelined main loop: prefetch k+1 before fmas of k ----
    float4 xv      = *reinterpret_cast<const float4*>(&Xs[0][tx * 4]);
    ulonglong2 w01 = *reinterpret_cast<const ulonglong2*>(&Ws[0][ty * 8]);
    ulonglong2 w23 = *reinterpret_cast<const ulonglong2*>(&Ws[0][ty * 8 + 4]);
#pragma unroll 4
    for (int k = 0; k < 64; ++k) {
        const int kn = (k + 1) & 63;
        float4 nxv      = *reinterpret_cast<const float4*>(&Xs[kn][tx * 4]);
        ulonglong2 nw01 = *reinterpret_cast<const ulonglong2*>(&Ws[kn][ty * 8]);
        ulonglong2 nw23 = *reinterpret_cast<const ulonglong2*>(&Ws[kn][ty * 8 + 4]);

        u64 wp[4] = {w01.x, w01.y, w23.x, w23.y};          // natural out-chan pairs
        u64 xd[4] = {pack2(xv.x, xv.x), pack2(xv.y, xv.y),
                     pack2(xv.z, xv.z), pack2(xv.w, xv.w)};
#pragma unroll
        for (int a = 0; a < 4; ++a)
#pragma unroll
            for (int p = 0; p < 4; ++p)
                fma2(acc2[a][p], wp[a], xd[p]);

        xv = nxv; w01 = nw01; w23 = nw23;
    }

    float* ob = g_qk + (size_t)t * BATCH * CHN * HW + (size_t)b * CHN * HW + p0;
#pragma unroll
    for (int ap = 0; ap < 4; ++ap) {
        float lo[4], hi[4];
#pragma unroll
        for (int p = 0; p < 4; ++p) unpack2(acc2[ap][p], lo[p], hi[p]);
        int o0 = ty * 8 + 2 * ap;
        *reinterpret_cast<float4*>(&ob[(size_t)o0 * HW + tx * 4]) =
            make_float4(lo[0], lo[1], lo[2], lo[3]);
        *reinterpret_cast<float4*>(&ob[(size_t)(o0 + 1) * HW + tx * 4]) =
            make_float4(hi[0], hi[1], hi[2], hi[3]);

        float s = 0.f, ss = 0.f;
#pragma unroll
        for (int p = 0; p < 4; ++p) {
            s  += lo[p] + hi[p];
            ss += lo[p] * lo[p] + hi[p] * hi[p];
        }
#pragma unroll
        for (int m = 16; m > 0; m >>= 1) {
            s  += __shfl_xor_sync(0xffffffffu, s,  m);
            ss += __shfl_xor_sync(0xffffffffu, ss, m);
        }
        if (tx == 0) {
            int g   = ty * 4 + ap;
            int idx = ((t * BATCH + b) * 32 + g) * 512 + blockIdx.x;
            g_psum[idx] = s;
            g_pss[idx]  = ss;
        }
    }
}

// ---------------- K2: finalize stats -> per-channel scale/bias --------------
__global__ void k_stats(const float* __restrict__ gq, const float* __restrict__ bq,
                        const float* __restrict__ gk, const float* __restrict__ bk)
{
    const int id  = blockIdx.x;
    const int tid = threadIdx.x;
    const float* ps = g_psum + (size_t)id * 512;
    const float* pq = g_pss  + (size_t)id * 512;
    float s  = ps[tid] + ps[tid + 256];
    float ss = pq[tid] + pq[tid + 256];
#pragma unroll
    for (int m = 16; m > 0; m >>= 1) {
        s  += __shfl_xor_sync(0xffffffffu, s,  m);
        ss += __shfl_xor_sync(0xffffffffu, ss, m);
    }
    __shared__ float sh[16];
    int w = tid >> 5;
    if ((tid & 31) == 0) { sh[w] = s; sh[8 + w] = ss; }
    __syncthreads();
    if (tid == 0) {
        float S = 0.f, SS = 0.f;
#pragma unroll
        for (int i = 0; i < 8; ++i) { S += sh[i]; SS += sh[8 + i]; }
        const float inv  = 1.0f / 131072.0f;
        float mean = S * inv;
        float var  = SS * inv - mean * mean;
        float rstd = rsqrtf(var + EPSV);
        int t = id >> 8, b = (id >> 5) & 7, g = id & 31;
        const float* ga = t ? gk : gq;
        const float* be = t ? bk : bq;
#pragma unroll
        for (int j = 0; j < 2; ++j) {
            int c = g * 2 + j;
            float sc = rstd * ga[c];
            g_scale[(t * BATCH + b) * CHN + c] = sc;
            g_bias [(t * BATCH + b) * CHN + c] = be[c] - mean * sc;
        }
    }
}

// ---------------- K3: windowed cross-attention + residual -------------------
// 128 threads = 1 window. 8x4 register tiles paired along q (natural smem
// pairs -> zero-cost fma2 operands), software-pipelined loads, 6 blocks/SM.
__global__ __launch_bounds__(128, 6) void k_attn(const float* __restrict__ xlow,
                                                 float* __restrict__ outp)
{
    extern __shared__ float sm[];
    const int wt = threadIdx.x;         // 0..127
    float (*bufA)[68] = reinterpret_cast<float(*)[68]>(sm);          // q -> K_T
    float (*bufK)[68] = reinterpret_cast<float(*)[68]>(sm + 4352);   // k -> P_T

    const int b  = blockIdx.y;
    const int wi = blockIdx.x;
    const int h0 = (wi >> 5) * 8, w0 = (wi & 31) * 8;
    const size_t gb = (size_t)b * CHN * HW;
    const float* qg = g_qk + gb;
    const float* kg = g_qk + (size_t)BATCH * CHN * HW + gb;
    const float* scq = g_scale + b * CHN;
    const float* biq = g_bias  + b * CHN;
    const float* sck = g_scale + (BATCH + b) * CHN;
    const float* bik = g_bias  + (BATCH + b) * CHN;

    // ---- load q,k with folded GroupNorm, channel-major [c][px], float4 ----
#pragma unroll
    for (int i = 0; i < 8; ++i) {
        int e = i * 128 + wt;
        int c = e >> 4, f = e & 15;          // px = 4f..4f+3
        size_t ga = (size_t)c * HW + (size_t)(h0 + (f >> 1)) * 256 + (w0 + (f & 1) * 4);
        float4 qv = *reinterpret_cast<const float4*>(qg + ga);
        float4 kv = *reinterpret_cast<const float4*>(kg + ga);
        float sq = scq[c], bq_ = biq[c];
        float sk = sck[c], bk_ = bik[c];
        *reinterpret_cast<float4*>(&bufA[c][f * 4]) =
            make_float4(qv.x * sq + bq_, qv.y * sq + bq_, qv.z * sq + bq_, qv.w * sq + bq_);
        *reinterpret_cast<float4*>(&bufK[c][f * 4]) =
            make_float4(kv.x * sk + bk_, kv.y * sk + bk_, kv.z * sk + bk_, kv.w * sk + bk_);
    }
    __syncthreads();

    const int tx = wt & 15;    // key/chan-col group (4 cols)
    const int ty = wt >> 4;    // query-row group (8 rows)

    // ---- GEMM1: S[q][k] = sum_c q[c][q]*k[c][k]; q paired, k dup'd --------
    u64 acc[4][4];             // acc[ip][j]: (S[2ip][j], S[2ip+1][j]) of tile
#pragma unroll
    for (int i = 0; i < 4; ++i)
#pragma unroll
        for (int j = 0; j < 4; ++j) acc[i][j] = 0ull;

    {
        ulonglong2 qA = *reinterpret_cast<const ulonglong2*>(&bufA[0][ty * 8]);
        ulonglong2 qB = *reinterpret_cast<const ulonglong2*>(&bufA[0][ty * 8 + 4]);
        float4 kv     = *reinterpret_cast<const float4*>(&bufK[0][tx * 4]);
#pragma unroll 4
        for (int k = 0; k < 64; ++k) {
            const int kn = (k + 1) & 63;
            ulonglong2 nqA = *reinterpret_cast<const ulonglong2*>(&bufA[kn][ty * 8]);
            ulonglong2 nqB = *reinterpret_cast<const ulonglong2*>(&bufA[kn][ty * 8 + 4]);
            float4 nkv     = *reinterpret_cast<const float4*>(&bufK[kn][tx * 4]);

            u64 qp[4] = {qA.x, qA.y, qB.x, qB.y};          // natural q-row pairs
            u64 kd[4] = {pack2(kv.x, kv.x), pack2(kv.y, kv.y),
                         pack2(kv.z, kv.z), pack2(kv.w, kv.w)};
#pragma unroll
            for (int ip = 0; ip < 4; ++ip)
#pragma unroll
                for (int j = 0; j < 4; ++j)
                    fma2(acc[ip][j], qp[ip], kd[j]);

            qA = nqA; qB = nqB; kv = nkv;
        }
    }

    // ---- softmax over key dim (4 local + 16-lane tx group), scale 1/8 ----
    float p[8][4];
#pragma unroll
    for (int ip = 0; ip < 4; ++ip)
#pragma unroll
        for (int j = 0; j < 4; ++j)
            unpack2(acc[ip][j], p[2 * ip][j], p[2 * ip + 1][j]);

#pragma unroll
    for (int i = 0; i < 8; ++i) {
#pragma unroll
        for (int j = 0; j < 4; ++j) p[i][j] *= 0.125f;
        float m = fmaxf(fmaxf(p[i][0], p[i][1]), fmaxf(p[i][2], p[i][3]));
#pragma unroll
        for (int msk = 8; msk > 0; msk >>= 1)
            m = fmaxf(m, __shfl_xor_sync(0xffffffffu, m, msk));
        float r = 0.f;
#pragma unroll
        for (int j = 0; j < 4; ++j) { p[i][j] = __expf(p[i][j] - m); r += p[i][j]; }
#pragma unroll
        for (int msk = 8; msk > 0; msk >>= 1)
            r += __shfl_xor_sync(0xffffffffu, r, msk);
        float inv = __fdividef(1.0f, r);
#pragma unroll
        for (int j = 0; j < 4; ++j) p[i][j] *= inv;
    }
    __syncthreads();   // GEMM1 reads of bufA/bufK complete

    // ---- K_T into bufA (q dead): bufA[px][c] = bufK[c][px] ----
    {
        const int col = wt & 63;
        const int r0  = (wt >> 6) * 32;
#pragma unroll 8
        for (int i = 0; i < 32; ++i) {
            float v = bufK[r0 + i][col];   // row-major read: conflict-free
            bufA[col][r0 + i] = v;         // column write: 4-way
        }
    }
    __syncthreads();   // all K_T reads of bufK done

    // ---- P_T into bufK directly from registers: bufK[k][q] = P[q][k] ----
#pragma unroll
    for (int i = 0; i < 8; ++i)
#pragma unroll
        for (int j = 0; j < 4; ++j)
            bufK[tx * 4 + j][ty * 8 + i] = p[i][j];
    __syncthreads();

    // ---- GEMM2: out[q][c] = sum_kp P_T[kp][q]*K_T[kp][c]; q paired --------
    u64 o2[4][4];              // o2[ip][j]: (out[2ip][j], out[2ip+1][j])
#pragma unroll
    for (int i = 0; i < 4; ++i)
#pragma unroll
        for (int j = 0; j < 4; ++j) o2[i][j] = 0ull;

    {
        ulonglong2 pA = *reinterpret_cast<const ulonglong2*>(&bufK[0][ty * 8]);
        ulonglong2 pB = *reinterpret_cast<const ulonglong2*>(&bufK[0][ty * 8 + 4]);
        float4 kv     = *reinterpret_cast<const float4*>(&bufA[0][tx * 4]);
#pragma unroll 4
        for (int k = 0; k < 64; ++k) {
            const int kn = (k + 1) & 63;
            ulonglong2 npA = *reinterpret_cast<const ulonglong2*>(&bufK[kn][ty * 8]);
            ulonglong2 npB = *reinterpret_cast<const ulonglong2*>(&bufK[kn][ty * 8 + 4]);
            float4 nkv     = *reinterpret_cast<const float4*>(&bufA[kn][tx * 4]);

            u64 pp[4] = {pA.x, pA.y, pB.x, pB.y};
            u64 kd[4] = {pack2(kv.x, kv.x), pack2(kv.y, kv.y),
                         pack2(kv.z, kv.z), pack2(kv.w, kv.w)};
#pragma unroll
            for (int ip = 0; ip < 4; ++ip)
#pragma unroll
                for (int j = 0; j < 4; ++j)
                    fma2(o2[ip][j], pp[ip], kd[j]);

            pA = npA; pB = npB; kv = nkv;
        }
    }

    // ---- epilogue: residual add + direct global stores ----
    // thread owns pixels q = ty*8..+7 (= window row ty), channels tx*4..+3
    const float* xb = xlow + gb;
    float* ob = outp + gb;
#pragma unroll
    for (int j = 0; j < 4; ++j) {
        float qv[8];
#pragma unroll
        for (int ip = 0; ip < 4; ++ip)
            unpack2(o2[ip][j], qv[2 * ip], qv[2 * ip + 1]);
        int c = tx * 4 + j;
        size_t base = (size_t)c * HW + (size_t)(h0 + ty) * 256 + w0;
        float4 r0 = *reinterpret_cast<const float4*>(xb + base);
        float4 r1 = *reinterpret_cast<const float4*>(xb + base + 4);
        *reinterpret_cast<float4*>(ob + base) =
            make_float4(qv[0] + r0.x, qv[1] + r0.y, qv[2] + r0.z, qv[3] + r0.w);
        *reinterpret_cast<float4*>(ob + base + 4) =
            make_float4(qv[4] + r1.x, qv[5] + r1.y, qv[6] + r1.z, qv[7] + r1.w);
    }
}

// ---------------- launch -----------------------------------------------------
extern "C" void kernel_launch(void* const* d_in, const int* in_sizes, int n_in,
                              void* d_out, int out_size)
{
    (void)in_sizes; (void)n_in; (void)out_size;
    const float* x_low  = (const float*)d_in[0];
    const float* x_high = (const float*)d_in[1];
    const float* Wq = (const float*)d_in[2];
    const float* Wk = (const float*)d_in[3];
    const float* gq = (const float*)d_in[4];
    const float* bq = (const float*)d_in[5];
    const float* gk = (const float*)d_in[6];
    const float* bk = (const float*)d_in[7];
    float* out = (float*)d_out;

    const int attn_smem = 2 * 64 * 68 * 4;   // 34816 B per window/block
    cudaFuncSetAttribute(k_attn, cudaFuncAttributeMaxDynamicSharedMemorySize, attn_smem);

    k_wt  <<<2, 256>>>(Wq, Wk);
    k_conv<<<dim3(512, BATCH, 2), 256>>>(x_low, x_high);
    k_stats<<<512, 256>>>(gq, bq, gk, bk);
    k_attn<<<dim3(1024, BATCH), 128, attn_smem>>>(x_low, out);
}